// round 1
// baseline (speedup 1.0000x reference)
#include <cuda_runtime.h>

#define BB 256
#define TT 1024
#define HH 64
#define GG 256   // 4*H gates

// Inter-layer activations (ping-pong). 2 x 64 MB device globals (no allocs).
__device__ float g_bufA[BB * TT * HH];
__device__ float g_bufB[BB * TT * HH];

__device__ __forceinline__ float sigf(float x) {
    x = fminf(fmaxf(x, -30.f), 30.f);
    return 1.0f / (1.0f + __expf(-x));
}
__device__ __forceinline__ float tanhf_fast(float x) {
    x = fminf(fmaxf(x, -15.f), 15.f);
    float e = __expf(-2.0f * x);
    return (1.0f - e) / (1.0f + e);
}

// Blackwell packed fp32 FMA (FFMA2) — only reachable via PTX.
#define FFMA2(acc, a, b) \
    asm("fma.rn.f32x2 %0, %1, %2, %0;" : "+l"(acc) : "l"(a), "l"(b))

// One LSTM layer scan. Grid: 128 CTAs x 256 threads; each CTA owns 2 batch rows.
// Thread g owns gate-row g (of 256): W_ih row + W_hh row live in registers as
// packed f32x2 pairs. z = [x_t, h_{t-1}] broadcast from smem (LDS.128).
template <bool FIRST>
__global__ void __launch_bounds__(256, 1)
lstm_scan(const float* __restrict__ xin,   // FIRST: [B,T,1] else [B,T,64]
          const float* __restrict__ wih,   // FIRST: [256,1] else [256,64]
          const float* __restrict__ whh,   // [256,64]
          const float* __restrict__ bih,   // [256]
          const float* __restrict__ bhh,   // [256]
          float* __restrict__ hout)        // [B,T,64]
{
    const int g  = threadIdx.x;
    const int b0 = blockIdx.x * 2;

    __shared__ __align__(16) float xs[2][64];
    __shared__ __align__(16) float hs[2][64];
    __shared__ float gsm[2][256];

    // Load weights into registers (packed pairs). Rows are 256B-aligned.
    unsigned long long wih2[32];
    unsigned long long whh2[32];
    float wih0s = 0.f;
    if (FIRST) {
        wih0s = wih[g];
    } else {
        const unsigned long long* wr =
            reinterpret_cast<const unsigned long long*>(wih + g * 64);
        #pragma unroll
        for (int k = 0; k < 32; k++) wih2[k] = wr[k];
    }
    {
        const unsigned long long* wr =
            reinterpret_cast<const unsigned long long*>(whh + g * 64);
        #pragma unroll
        for (int k = 0; k < 32; k++) whh2[k] = wr[k];
    }
    const float bsum = bih[g] + bhh[g];

    // Init h=0, c=0, stage x at t=0.
    if (g < 128) {
        int b = g >> 6, j = g & 63;
        hs[b][j] = 0.f;
        if (FIRST) { if (j == 0) xs[b][0] = xin[(b0 + b) * TT]; }
        else       { xs[b][j] = xin[((size_t)(b0 + b) * TT) * 64 + j]; }
    }
    float c = 0.f;  // cell state (valid for g < 128)
    __syncthreads();

    for (int t = 0; t < TT; ++t) {
        // Prefetch x_{t+1} into a register; FMA loop below hides the latency.
        float xnext = 0.f;
        if (t + 1 < TT && g < 128) {
            int b = g >> 6, j = g & 63;
            if (FIRST) { if (j == 0) xnext = xin[(b0 + b) * TT + t + 1]; }
            else       { xnext = xin[((size_t)(b0 + b) * TT + t + 1) * 64 + j]; }
        }

        // gates[b][g] = bsum + W_ih[g]·x_t[b] + W_hh[g]·h[b]
        unsigned long long a0p = 0ULL, a1p = 0ULL;  // packed (even-k, odd-k) partials
        if (!FIRST) {
            const ulonglong2* x0 = reinterpret_cast<const ulonglong2*>(xs[0]);
            const ulonglong2* x1 = reinterpret_cast<const ulonglong2*>(xs[1]);
            #pragma unroll
            for (int k = 0; k < 16; k++) {
                ulonglong2 v0 = x0[k];
                ulonglong2 v1 = x1[k];
                FFMA2(a0p, wih2[2 * k],     v0.x);
                FFMA2(a1p, wih2[2 * k],     v1.x);
                FFMA2(a0p, wih2[2 * k + 1], v0.y);
                FFMA2(a1p, wih2[2 * k + 1], v1.y);
            }
        }
        {
            const ulonglong2* h0 = reinterpret_cast<const ulonglong2*>(hs[0]);
            const ulonglong2* h1 = reinterpret_cast<const ulonglong2*>(hs[1]);
            #pragma unroll
            for (int k = 0; k < 16; k++) {
                ulonglong2 v0 = h0[k];
                ulonglong2 v1 = h1[k];
                FFMA2(a0p, whh2[2 * k],     v0.x);
                FFMA2(a1p, whh2[2 * k],     v1.x);
                FFMA2(a0p, whh2[2 * k + 1], v0.y);
                FFMA2(a1p, whh2[2 * k + 1], v1.y);
            }
        }
        float lo0, hi0, lo1, hi1;
        asm("mov.b64 {%0,%1}, %2;" : "=f"(lo0), "=f"(hi0) : "l"(a0p));
        asm("mov.b64 {%0,%1}, %2;" : "=f"(lo1), "=f"(hi1) : "l"(a1p));
        float a0 = bsum + lo0 + hi0;
        float a1 = bsum + lo1 + hi1;
        if (FIRST) {
            a0 += wih0s * xs[0][0];
            a1 += wih0s * xs[1][0];
        }

        // Gate order i,f,g,o: rows [0,64)=i [64,128)=f [128,192)=g [192,256)=o
        float v0, v1;
        if ((g >> 6) == 2) { v0 = tanhf_fast(a0); v1 = tanhf_fast(a1); }
        else               { v0 = sigf(a0);       v1 = sigf(a1); }
        gsm[0][g] = v0;
        gsm[1][g] = v1;
        __syncthreads();

        // State update: threads 0..127 own (b, unit j).
        if (g < 128) {
            int b = g >> 6, j = g & 63;
            float iv = gsm[b][j];
            float fv = gsm[b][64 + j];
            float gv = gsm[b][128 + j];
            float ov = gsm[b][192 + j];
            c = fv * c + iv * gv;
            float hval = ov * tanhf_fast(c);
            hs[b][j] = hval;
            hout[(((size_t)(b0 + b)) * TT + t) * 64 + j] = hval;
            if (FIRST) { if (j == 0) xs[b][0] = xnext; }
            else       { xs[b][j] = xnext; }
        }
        __syncthreads();
    }
}

// Head: out = relu(relu(h) @ W1^T + b1) @ W2^T + b2, per (b,t) position.
// One warp per position; W1 transposed in smem (conflict-free LDS).
__global__ void __launch_bounds__(256)
fc_kernel(const float* __restrict__ hin,  // [B,T,64]
          const float* __restrict__ W1,   // [64,64]
          const float* __restrict__ b1,   // [64]
          const float* __restrict__ W2,   // [1,64]
          const float* __restrict__ b2,   // [1]
          float* __restrict__ out)        // [B*T]
{
    __shared__ float W1T[64 * 64];
    __shared__ float b1s[64];
    __shared__ float w2s[64];
    __shared__ float hsm[8][64];

    for (int i = threadIdx.x; i < 64 * 64; i += 256) {
        int j = i >> 6, k = i & 63;
        W1T[k * 64 + j] = W1[j * 64 + k];
    }
    if (threadIdx.x < 64) {
        b1s[threadIdx.x] = b1[threadIdx.x];
        w2s[threadIdx.x] = W2[threadIdx.x];
    }
    __syncthreads();
    const float b2v = b2[0];

    const int warp = threadIdx.x >> 5, lane = threadIdx.x & 31;
    for (int p = blockIdx.x * 8 + warp; p < BB * TT; p += gridDim.x * 8) {
        float h0 = fmaxf(hin[(size_t)p * 64 + lane], 0.f);
        float h1 = fmaxf(hin[(size_t)p * 64 + 32 + lane], 0.f);
        hsm[warp][lane]      = h0;
        hsm[warp][lane + 32] = h1;
        __syncwarp();
        float y0 = b1s[lane], y1 = b1s[lane + 32];
        #pragma unroll
        for (int k = 0; k < 64; k++) {
            float hv = hsm[warp][k];
            y0 = fmaf(W1T[k * 64 + lane],      hv, y0);
            y1 = fmaf(W1T[k * 64 + lane + 32], hv, y1);
        }
        y0 = fmaxf(y0, 0.f);
        y1 = fmaxf(y1, 0.f);
        float part = y0 * w2s[lane] + y1 * w2s[lane + 32];
        #pragma unroll
        for (int off = 16; off; off >>= 1)
            part += __shfl_down_sync(0xffffffffu, part, off);
        if (lane == 0) out[p] = part + b2v;
        __syncwarp();
    }
}

extern "C" void kernel_launch(void* const* d_in, const int* in_sizes, int n_in,
                              void* d_out, int out_size)
{
    const float* x    = (const float*)d_in[0];  // [256,1024,1]
    const float* wih0 = (const float*)d_in[1];  // [256,1]
    const float* wihR = (const float*)d_in[2];  // [4,256,64]
    const float* whh  = (const float*)d_in[3];  // [5,256,64]
    const float* bih  = (const float*)d_in[4];  // [5,256]
    const float* bhh  = (const float*)d_in[5];  // [5,256]
    const float* W1   = (const float*)d_in[6];  // [64,64]
    const float* b1   = (const float*)d_in[7];  // [64]
    const float* W2   = (const float*)d_in[8];  // [1,64]
    const float* b2   = (const float*)d_in[9];  // [1]
    float* out = (float*)d_out;                 // [256,1024,1]
    (void)in_sizes; (void)n_in; (void)out_size; // future == 0 per setup

    void *pA = nullptr, *pB = nullptr;
    cudaGetSymbolAddress(&pA, g_bufA);
    cudaGetSymbolAddress(&pB, g_bufB);
    float* bufA = (float*)pA;
    float* bufB = (float*)pB;

    const int WSZ = GG * HH;  // per-layer weight block
    lstm_scan<true ><<<128, 256>>>(x,    wih0,            whh,           bih,          bhh,          bufA);
    lstm_scan<false><<<128, 256>>>(bufA, wihR + 0 * WSZ,  whh + 1 * WSZ, bih + 1 * GG, bhh + 1 * GG, bufB);
    lstm_scan<false><<<128, 256>>>(bufB, wihR + 1 * WSZ,  whh + 2 * WSZ, bih + 2 * GG, bhh + 2 * GG, bufA);
    lstm_scan<false><<<128, 256>>>(bufA, wihR + 2 * WSZ,  whh + 3 * WSZ, bih + 3 * GG, bhh + 3 * GG, bufB);
    lstm_scan<false><<<128, 256>>>(bufB, wihR + 3 * WSZ,  whh + 4 * WSZ, bih + 4 * GG, bhh + 4 * GG, bufA);
    fc_kernel<<<2048, 256>>>(bufA, W1, b1, W2, b2, out);
}